// round 6
// baseline (speedup 1.0000x reference)
#include <cuda_runtime.h>
#include <cuda_bf16.h>
#include <cstdint>

// FlowBasedDensityPotential: energy = 0.5 * sum(|grad phi|^2), central diffs
// (one-sided at boundaries) on a 2048x2048 f32 grid. 'pos' input is dead.
//
// R5: R2's front-batched-load design + __launch_bounds__(256, 2).
// R2 failed because bare __launch_bounds__(256) let ptxas cap at 32 regs and
// re-serialize the 14 loads (MLP stayed ~2; identical time to R1). The
// minBlocksPerMultiprocessor=2 hint raises the register ceiling to 128,
// letting ptxas keep all 6 float4 rows + 8 halo scalars live -> MLP ~14 per
// thread, ~560 loads in flight per SM at 5 CTAs/SM.

#define NX 2048
#define NY 2048
#define RPT 4                         // rows per thread
#define BLOCK 256
#define CHUNKS_PER_BAND (NY / 4)      // 512 float4 chunks per row band
#define NUM_BANDS (NX / RPT)          // 512
#define TOTAL_THREADS (CHUNKS_PER_BAND * NUM_BANDS)   // 262144
#define NUM_BLOCKS (TOTAL_THREADS / BLOCK)            // 1024

__device__ double       g_partials[NUM_BLOCKS];
__device__ unsigned int g_ticket = 0;

__global__ void __launch_bounds__(BLOCK, 2)
flow_energy_kernel(const float* __restrict__ phi, float* __restrict__ out)
{
    const int t    = blockIdx.x * BLOCK + threadIdx.x;
    const int jc   = t & (CHUNKS_PER_BAND - 1);   // chunk index along y (lane-contiguous)
    const int band = t >> 9;                      // row band index
    const int j0   = jc * 4;
    const int i0   = band * RPT;

    const float C1 = 1024.0f;   // 1/(2h), h = 1/2048
    const float C2 = 2048.0f;   // 1/h (one-sided boundary)

    // ---- FRONT-BATCHED LOADS: all 14 issued before any compute ----
    // Rows i0-1 .. i0+4, row index clamped (clamped rows never used by the
    // one-sided boundary formulas).
    float4 a[RPT + 2];
    #pragma unroll
    for (int k = 0; k < RPT + 2; ++k) {
        int ri = i0 - 1 + k;
        ri = ri < 0 ? 0 : (ri > NX - 1 ? NX - 1 : ri);
        a[k] = *reinterpret_cast<const float4*>(phi + (size_t)ri * NY + j0);
    }
    // Halo scalars for each computed row; columns clamped (unused at y-edges).
    const int jl = j0 > 0 ? j0 - 1 : 0;
    const int jr = j0 + 4 < NY ? j0 + 4 : NY - 1;
    float hl[RPT], hr[RPT];
    #pragma unroll
    for (int r = 0; r < RPT; ++r) {
        const size_t row = (size_t)(i0 + r) * NY;
        hl[r] = phi[row + jl];
        hr[r] = phi[row + jr];
    }

    // ---- COMPUTE (two accumulators to shorten the FFMA chain) ----
    float acc0 = 0.0f, acc1 = 0.0f;
    #pragma unroll
    for (int r = 0; r < RPT; ++r) {
        const int i = i0 + r;
        const float4 prev = a[r];
        const float4 cur  = a[r + 1];
        const float4 next = a[r + 2];

        float4 dx;
        if (i == 0) {
            dx.x = (next.x - cur.x) * C2;
            dx.y = (next.y - cur.y) * C2;
            dx.z = (next.z - cur.z) * C2;
            dx.w = (next.w - cur.w) * C2;
        } else if (i == NX - 1) {
            dx.x = (cur.x - prev.x) * C2;
            dx.y = (cur.y - prev.y) * C2;
            dx.z = (cur.z - prev.z) * C2;
            dx.w = (cur.w - prev.w) * C2;
        } else {
            dx.x = (next.x - prev.x) * C1;
            dx.y = (next.y - prev.y) * C1;
            dx.z = (next.z - prev.z) * C1;
            dx.w = (next.w - prev.w) * C1;
        }

        const float dy0 = (j0 == 0)      ? (cur.y - cur.x) * C2 : (cur.y - hl[r]) * C1;
        const float dy1 = (cur.z - cur.x) * C1;
        const float dy2 = (cur.w - cur.y) * C1;
        const float dy3 = (j0 + 4 == NY) ? (cur.w - cur.z) * C2 : (hr[r] - cur.z) * C1;

        acc0 += dx.x * dx.x + dy0 * dy0;
        acc1 += dx.y * dx.y + dy1 * dy1;
        acc0 += dx.z * dx.z + dy2 * dy2;
        acc1 += dx.w * dx.w + dy3 * dy3;
    }
    float acc = acc0 + acc1;

    // ---- block reduction (float tree; <= 16 terms/thread) ----
    #pragma unroll
    for (int off = 16; off; off >>= 1)
        acc += __shfl_xor_sync(0xffffffffu, acc, off);

    __shared__ float  s_warp[BLOCK / 32];
    __shared__ bool   s_is_last;
    if ((threadIdx.x & 31) == 0)
        s_warp[threadIdx.x >> 5] = acc;
    __syncthreads();

    if (threadIdx.x < 32) {
        float v = (threadIdx.x < BLOCK / 32) ? s_warp[threadIdx.x] : 0.0f;
        #pragma unroll
        for (int off = 4; off; off >>= 1)
            v += __shfl_xor_sync(0xffffffffu, v, off);
        if (threadIdx.x == 0) {
            g_partials[blockIdx.x] = (double)v;
            __threadfence();
            unsigned int tk = atomicAdd(&g_ticket, 1u);
            s_is_last = (tk == (unsigned int)(gridDim.x - 1));
        }
    }
    __syncthreads();

    // ---- last block: sum the 1024 double partials, write scalar, reset ----
    if (s_is_last) {
        double d = 0.0;
        for (int k = threadIdx.x; k < NUM_BLOCKS; k += BLOCK)
            d += g_partials[k];
        #pragma unroll
        for (int off = 16; off; off >>= 1)
            d += __shfl_xor_sync(0xffffffffu, d, off);

        __shared__ double s_dwarp[BLOCK / 32];
        if ((threadIdx.x & 31) == 0)
            s_dwarp[threadIdx.x >> 5] = d;
        __syncthreads();
        if (threadIdx.x < 32) {
            double v = (threadIdx.x < BLOCK / 32) ? s_dwarp[threadIdx.x] : 0.0;
            #pragma unroll
            for (int off = 4; off; off >>= 1)
                v += __shfl_xor_sync(0xffffffffu, v, off);
            if (threadIdx.x == 0) {
                out[0] = (float)(0.5 * v);
                g_ticket = 0;   // reset for next (graph-replayed) launch
            }
        }
    }
}

extern "C" void kernel_launch(void* const* d_in, const int* in_sizes, int n_in,
                              void* d_out, int out_size)
{
    // Select phi by element count (2048*2048); 'pos' (2,000,000 elems) unused.
    const float* phi = nullptr;
    for (int i = 0; i < n_in; ++i) {
        if (in_sizes[i] == NX * NY) { phi = (const float*)d_in[i]; break; }
    }
    if (!phi) phi = (const float*)d_in[n_in - 1];

    flow_energy_kernel<<<NUM_BLOCKS, BLOCK>>>(phi, (float*)d_out);
}

// round 8
// speedup vs baseline: 1.0029x; 1.0029x over previous
#include <cuda_runtime.h>
#include <cuda_bf16.h>
#include <cstdint>

// FlowBasedDensityPotential: energy = 0.5 * sum(|grad phi|^2), central diffs
// (one-sided at boundaries) on 2048x2048 f32. 'pos' input is dead.
//
// R7 = R6 resubmitted verbatim (R6 never ran: GB300 container infra failure).
// R6: (1) exact single wave: grid 592 = 4*148 with __launch_bounds__(256,4)
//     -> 4 CTAs/SM, zero tail (R5's 1.38-wave tail cost ~40%).
//     (2) fewer warp-instructions: y-halos via __shfl from adjacent lanes
//     (8 scalar LDG/thread -> 2 predicated LDG per warp-row), and factored
//     constants (accumulate raw squared diffs; boundary diffs doubled since
//     C2 = 2*C1; single 0.5*C1^2 scale at the end).

#define NX 2048
#define NY 2048
#define RPT 4
#define BLOCK 256
#define NUM_BLOCKS 592                           // 4 * 148 SMs: one exact wave
#define TOTAL_TASKS ((NY / 4) * (NX / RPT))      // 512 * 512 = 262144
#define FINAL_SCALE 524288.0                     // 0.5 * (1/(2h))^2 = 0.5*1024^2

__device__ double       g_partials[NUM_BLOCKS];
__device__ unsigned int g_ticket = 0;

__global__ void __launch_bounds__(BLOCK, 4)
flow_energy_kernel(const float* __restrict__ phi, float* __restrict__ out)
{
    const int tid     = threadIdx.x;
    const int lane    = tid & 31;
    const int t       = blockIdx.x * BLOCK + tid;
    const int nthread = NUM_BLOCKS * BLOCK;      // 151552

    float acc = 0.0f;

    for (int task = t; task < TOTAL_TASKS; task += nthread) {
        const int jc = task & 511;               // 4-col chunk (lane-contiguous)
        const int i0 = (task >> 9) * RPT;        // first row of band
        const int j0 = jc * 4;

        // Front-batched row loads: rows i0-1 .. i0+4 (clamped rows unused).
        float4 a[RPT + 2];
        #pragma unroll
        for (int k = 0; k < RPT + 2; ++k) {
            int ri = i0 - 1 + k;
            ri = ri < 0 ? 0 : (ri > NX - 1 ? NX - 1 : ri);
            a[k] = *reinterpret_cast<const float4*>(phi + (size_t)ri * NY + j0);
        }

        #pragma unroll
        for (int r = 0; r < RPT; ++r) {
            const int i = i0 + r;
            const size_t row = (size_t)i * NY;
            const float4 prev = a[r];
            const float4 cur  = a[r + 1];
            const float4 next = a[r + 2];

            // x-direction raw diffs (boundary: one-sided, doubled)
            float ex, ey, ez, ew;
            if (i == 0) {
                ex = (next.x - cur.x) * 2.0f;
                ey = (next.y - cur.y) * 2.0f;
                ez = (next.z - cur.z) * 2.0f;
                ew = (next.w - cur.w) * 2.0f;
            } else if (i == NX - 1) {
                ex = (cur.x - prev.x) * 2.0f;
                ey = (cur.y - prev.y) * 2.0f;
                ez = (cur.z - prev.z) * 2.0f;
                ew = (cur.w - prev.w) * 2.0f;
            } else {
                ex = next.x - prev.x;
                ey = next.y - prev.y;
                ez = next.z - prev.z;
                ew = next.w - prev.w;
            }

            // y-direction: halos from adjacent lanes via shfl; warp-edge lanes
            // fall back to a tiny predicated scalar load.
            float left  = __shfl_up_sync(0xffffffffu, cur.w, 1);
            float right = __shfl_down_sync(0xffffffffu, cur.x, 1);
            if (lane == 0 && j0 > 0)
                left = phi[row + j0 - 1];
            if (lane == 31 && j0 + 4 < NY)
                right = phi[row + j0 + 4];

            const float d0 = (j0 == 0)      ? (cur.y - cur.x) * 2.0f : (cur.y - left);
            const float d1 = cur.z - cur.x;
            const float d2 = cur.w - cur.y;
            const float d3 = (j0 + 4 == NY) ? (cur.w - cur.z) * 2.0f : (right - cur.z);

            acc += ex * ex + d0 * d0;
            acc += ey * ey + d1 * d1;
            acc += ez * ez + d2 * d2;
            acc += ew * ew + d3 * d3;
        }
    }

    // ---- block reduction ----
    #pragma unroll
    for (int off = 16; off; off >>= 1)
        acc += __shfl_xor_sync(0xffffffffu, acc, off);

    __shared__ float  s_warp[BLOCK / 32];
    __shared__ bool   s_is_last;
    if ((tid & 31) == 0)
        s_warp[tid >> 5] = acc;
    __syncthreads();

    if (tid < 32) {
        float v = (tid < BLOCK / 32) ? s_warp[tid] : 0.0f;
        #pragma unroll
        for (int off = 4; off; off >>= 1)
            v += __shfl_xor_sync(0xffffffffu, v, off);
        if (tid == 0) {
            g_partials[blockIdx.x] = (double)v;
            __threadfence();
            unsigned int tk = atomicAdd(&g_ticket, 1u);
            s_is_last = (tk == (unsigned int)(gridDim.x - 1));
        }
    }
    __syncthreads();

    // ---- last block: sum 592 double partials, scale, write, reset ----
    if (s_is_last) {
        double d = 0.0;
        for (int k = tid; k < NUM_BLOCKS; k += BLOCK)
            d += g_partials[k];
        #pragma unroll
        for (int off = 16; off; off >>= 1)
            d += __shfl_xor_sync(0xffffffffu, d, off);

        __shared__ double s_dwarp[BLOCK / 32];
        if ((tid & 31) == 0)
            s_dwarp[tid >> 5] = d;
        __syncthreads();
        if (tid < 32) {
            double v = (tid < BLOCK / 32) ? s_dwarp[tid] : 0.0;
            #pragma unroll
            for (int off = 4; off; off >>= 1)
                v += __shfl_xor_sync(0xffffffffu, v, off);
            if (tid == 0) {
                out[0] = (float)(v * FINAL_SCALE);
                g_ticket = 0;   // reset for next (graph-replayed) launch
            }
        }
    }
}

extern "C" void kernel_launch(void* const* d_in, const int* in_sizes, int n_in,
                              void* d_out, int out_size)
{
    // Select phi by element count (2048*2048); 'pos' (2,000,000 elems) unused.
    const float* phi = nullptr;
    for (int i = 0; i < n_in; ++i) {
        if (in_sizes[i] == NX * NY) { phi = (const float*)d_in[i]; break; }
    }
    if (!phi) phi = (const float*)d_in[n_in - 1];

    flow_energy_kernel<<<NUM_BLOCKS, BLOCK>>>(phi, (float*)d_out);
}